// round 1
// baseline (speedup 1.0000x reference)
#include <cuda_runtime.h>

#define Bsz 2
#define Ssz 2048
#define Dsz 1024
#define Hsz 16
#define HDsz 64
#define Msz (Bsz*Ssz)   // 4096

// scratch (allocation-free): q,k,v in [B,H,S,HD], z in [B,S,D]
__device__ float g_q[Bsz*Hsz*Ssz*HDsz];
__device__ float g_k[Bsz*Hsz*Ssz*HDsz];
__device__ float g_v[Bsz*Hsz*Ssz*HDsz];
__device__ float g_z[Msz*Dsz];

// ---------------- SGEMM (NT): C[m,n] = sum_k A[m,k]*W[n,k] + bias[n] ----------------
// BM=BN=128, BK=16, 256 threads, 8x8 per thread.

#define BM 128
#define BN 128
#define BKT 16

__global__ __launch_bounds__(256) void proj_kernel(
    const float* __restrict__ X,
    const float* __restrict__ Wq, const float* __restrict__ bq,
    const float* __restrict__ Wk, const float* __restrict__ bk,
    const float* __restrict__ Wv, const float* __restrict__ bv)
{
    __shared__ float As[BKT][BM + 4];
    __shared__ float Bs[BKT][BN + 4];

    const int which = blockIdx.z;
    const float* __restrict__ W    = (which == 0) ? Wq : (which == 1) ? Wk : Wv;
    const float* __restrict__ bias = (which == 0) ? bq : (which == 1) ? bk : bv;
    float* __restrict__ out        = (which == 0) ? g_q : (which == 1) ? g_k : g_v;

    const int tid = threadIdx.x;
    const int tx = tid & 15, ty = tid >> 4;
    const int m0 = blockIdx.y * BM, n0 = blockIdx.x * BN;
    const float* Aptr = X + (size_t)m0 * Dsz;
    const float* Bptr = W + (size_t)n0 * Dsz;

    float acc[8][8];
#pragma unroll
    for (int i = 0; i < 8; i++)
#pragma unroll
        for (int j = 0; j < 8; j++) acc[i][j] = 0.f;

    for (int k0 = 0; k0 < Dsz; k0 += BKT) {
#pragma unroll
        for (int p = 0; p < 2; p++) {
            int idx = tid + p * 256;        // 0..511
            int row = idx >> 2;             // 0..127
            int c4  = (idx & 3) << 2;       // 0,4,8,12
            float4 va = *(const float4*)(Aptr + (size_t)row * Dsz + k0 + c4);
            As[c4 + 0][row] = va.x; As[c4 + 1][row] = va.y;
            As[c4 + 2][row] = va.z; As[c4 + 3][row] = va.w;
            float4 vb = *(const float4*)(Bptr + (size_t)row * Dsz + k0 + c4);
            Bs[c4 + 0][row] = vb.x; Bs[c4 + 1][row] = vb.y;
            Bs[c4 + 2][row] = vb.z; Bs[c4 + 3][row] = vb.w;
        }
        __syncthreads();

#pragma unroll
        for (int kk = 0; kk < BKT; kk++) {
            float a[8], bb[8];
            *(float4*)&a[0]  = *(const float4*)&As[kk][ty * 8];
            *(float4*)&a[4]  = *(const float4*)&As[kk][ty * 8 + 4];
            *(float4*)&bb[0] = *(const float4*)&Bs[kk][tx * 8];
            *(float4*)&bb[4] = *(const float4*)&Bs[kk][tx * 8 + 4];
#pragma unroll
            for (int i = 0; i < 8; i++)
#pragma unroll
                for (int j = 0; j < 8; j++)
                    acc[i][j] += a[i] * bb[j];
        }
        __syncthreads();
    }

    // epilogue: scatter to [B,H,S,HD] with bias
#pragma unroll
    for (int i = 0; i < 8; i++) {
        int m  = m0 + ty * 8 + i;
        int b_ = m >> 11;        // / 2048
        int s  = m & 2047;
#pragma unroll
        for (int j = 0; j < 8; j++) {
            int n = n0 + tx * 8 + j;
            int h = n >> 6;
            int e = n & 63;
            out[(((size_t)(b_ * Hsz + h) * Ssz) + s) * HDsz + e] = acc[i][j] + bias[n];
        }
    }
}

__global__ __launch_bounds__(256) void outproj_kernel(
    const float* __restrict__ Wo, const float* __restrict__ bo,
    float* __restrict__ out)
{
    __shared__ float As[BKT][BM + 4];
    __shared__ float Bs[BKT][BN + 4];

    const int tid = threadIdx.x;
    const int tx = tid & 15, ty = tid >> 4;
    const int m0 = blockIdx.y * BM, n0 = blockIdx.x * BN;
    const float* Aptr = g_z + (size_t)m0 * Dsz;
    const float* Bptr = Wo + (size_t)n0 * Dsz;

    float acc[8][8];
#pragma unroll
    for (int i = 0; i < 8; i++)
#pragma unroll
        for (int j = 0; j < 8; j++) acc[i][j] = 0.f;

    for (int k0 = 0; k0 < Dsz; k0 += BKT) {
#pragma unroll
        for (int p = 0; p < 2; p++) {
            int idx = tid + p * 256;
            int row = idx >> 2;
            int c4  = (idx & 3) << 2;
            float4 va = *(const float4*)(Aptr + (size_t)row * Dsz + k0 + c4);
            As[c4 + 0][row] = va.x; As[c4 + 1][row] = va.y;
            As[c4 + 2][row] = va.z; As[c4 + 3][row] = va.w;
            float4 vb = *(const float4*)(Bptr + (size_t)row * Dsz + k0 + c4);
            Bs[c4 + 0][row] = vb.x; Bs[c4 + 1][row] = vb.y;
            Bs[c4 + 2][row] = vb.z; Bs[c4 + 3][row] = vb.w;
        }
        __syncthreads();

#pragma unroll
        for (int kk = 0; kk < BKT; kk++) {
            float a[8], bb[8];
            *(float4*)&a[0]  = *(const float4*)&As[kk][ty * 8];
            *(float4*)&a[4]  = *(const float4*)&As[kk][ty * 8 + 4];
            *(float4*)&bb[0] = *(const float4*)&Bs[kk][tx * 8];
            *(float4*)&bb[4] = *(const float4*)&Bs[kk][tx * 8 + 4];
#pragma unroll
            for (int i = 0; i < 8; i++)
#pragma unroll
                for (int j = 0; j < 8; j++)
                    acc[i][j] += a[i] * bb[j];
        }
        __syncthreads();
    }

#pragma unroll
    for (int i = 0; i < 8; i++) {
        int m = m0 + ty * 8 + i;
#pragma unroll
        for (int j = 0; j < 8; j++) {
            int n = n0 + tx * 8 + j;
            out[(size_t)m * Dsz + n] = acc[i][j] + bo[n];
        }
    }
}

// ---------------- fused causal flash attention (fp32) ----------------
// One block per (b, h, 64-row Q tile). 256 threads as 16x16; 4x4 fragment each.
// Shared: Qs[d][r] 64x65, Ks[d][c] 64x65, Ps[k][r] 64x65, Vs[k][c] 64x68 (dynamic).

#define AQ 64
#define AK 64
#define QS_STRIDE 65
#define VS_STRIDE 68
#define SMEM_FLOATS (3 * 64 * QS_STRIDE + 64 * VS_STRIDE)  // 16832
#define SMEM_BYTES (SMEM_FLOATS * 4)                        // 67328

__global__ __launch_bounds__(256) void attn_kernel()
{
    extern __shared__ float sm[];
    float* Qs = sm;                       // [64][65]  (d-major)
    float* Ks = sm + 64 * QS_STRIDE;      // [64][65]  (d-major)
    float* Ps = sm + 2 * 64 * QS_STRIDE;  // [64][65]  (k-major)
    float* Vs = sm + 3 * 64 * QS_STRIDE;  // [64][68]  (k-major, natural)

    const int tid = threadIdx.x;
    const int tx = tid & 15, ty = tid >> 4;
    const int q0 = blockIdx.x * AQ;
    const int h  = blockIdx.y;
    const int b  = blockIdx.z;
    const int r0 = ty * 4, c0 = tx * 4;

    const size_t head_off = (size_t)(b * Hsz + h) * Ssz * HDsz;
    const float* Qp = g_q + head_off;
    const float* Kp = g_k + head_off;
    const float* Vp = g_v + head_off;

    // load Q tile transposed: Qs[d][r]
#pragma unroll
    for (int p = 0; p < 4; p++) {
        int idx = tid + p * 256;          // 0..1023
        int row = idx >> 4;               // 0..63
        int d4  = (idx & 15) << 2;        // 0..60
        float4 v = *(const float4*)(Qp + (size_t)(q0 + row) * HDsz + d4);
        Qs[(d4 + 0) * QS_STRIDE + row] = v.x;
        Qs[(d4 + 1) * QS_STRIDE + row] = v.y;
        Qs[(d4 + 2) * QS_STRIDE + row] = v.z;
        Qs[(d4 + 3) * QS_STRIDE + row] = v.w;
    }

    float mrow[4], lrow[4], o[4][4];
#pragma unroll
    for (int i = 0; i < 4; i++) {
        mrow[i] = -1e30f; lrow[i] = 0.f;
#pragma unroll
        for (int j = 0; j < 4; j++) o[i][j] = 0.f;
    }
    __syncthreads();

    const int nkt = q0 / AK + 1;
    const float scale = 0.125f;  // 1/sqrt(64)

    for (int jt = 0; jt < nkt; jt++) {
        const int k0 = jt * AK;

        // load K transposed into Ks[d][c], V natural into Vs[k][c]
#pragma unroll
        for (int p = 0; p < 4; p++) {
            int idx = tid + p * 256;
            int row = idx >> 4;
            int d4  = (idx & 15) << 2;
            float4 kv = *(const float4*)(Kp + (size_t)(k0 + row) * HDsz + d4);
            Ks[(d4 + 0) * QS_STRIDE + row] = kv.x;
            Ks[(d4 + 1) * QS_STRIDE + row] = kv.y;
            Ks[(d4 + 2) * QS_STRIDE + row] = kv.z;
            Ks[(d4 + 3) * QS_STRIDE + row] = kv.w;
            float4 vv = *(const float4*)(Vp + (size_t)(k0 + row) * HDsz + d4);
            *(float4*)&Vs[row * VS_STRIDE + d4] = vv;
        }
        __syncthreads();

        // S fragment = Q @ K^T
        float s[4][4];
#pragma unroll
        for (int i = 0; i < 4; i++)
#pragma unroll
            for (int j = 0; j < 4; j++) s[i][j] = 0.f;

#pragma unroll 16
        for (int d = 0; d < 64; d++) {
            float a[4], bb[4];
#pragma unroll
            for (int i = 0; i < 4; i++) a[i]  = Qs[d * QS_STRIDE + r0 + i];
#pragma unroll
            for (int j = 0; j < 4; j++) bb[j] = Ks[d * QS_STRIDE + c0 + j];
#pragma unroll
            for (int i = 0; i < 4; i++)
#pragma unroll
                for (int j = 0; j < 4; j++)
                    s[i][j] += a[i] * bb[j];
        }

        // scale + causal mask (only diagonal tile can mask, since k0 <= q0)
        if (jt == nkt - 1) {
#pragma unroll
            for (int i = 0; i < 4; i++)
#pragma unroll
                for (int j = 0; j < 4; j++)
                    s[i][j] = (c0 + j <= r0 + i) ? s[i][j] * scale : -1e30f;
        } else {
#pragma unroll
            for (int i = 0; i < 4; i++)
#pragma unroll
                for (int j = 0; j < 4; j++)
                    s[i][j] *= scale;
        }

        // online softmax; row group = 16 lanes sharing ty
#pragma unroll
        for (int i = 0; i < 4; i++) {
            float v = s[i][0];
#pragma unroll
            for (int j = 1; j < 4; j++) v = fmaxf(v, s[i][j]);
#pragma unroll
            for (int off = 8; off; off >>= 1)
                v = fmaxf(v, __shfl_xor_sync(0xffffffffu, v, off, 16));
            float mnew = fmaxf(mrow[i], v);
            float corr = __expf(mrow[i] - mnew);
            float rs = 0.f;
#pragma unroll
            for (int j = 0; j < 4; j++) {
                float pv = __expf(s[i][j] - mnew);
                s[i][j] = pv;
                rs += pv;
            }
#pragma unroll
            for (int off = 8; off; off >>= 1)
                rs += __shfl_xor_sync(0xffffffffu, rs, off, 16);
            lrow[i] = lrow[i] * corr + rs;
#pragma unroll
            for (int j = 0; j < 4; j++) o[i][j] *= corr;
            mrow[i] = mnew;
        }

        // stage P transposed: Ps[k][r]
#pragma unroll
        for (int i = 0; i < 4; i++)
#pragma unroll
            for (int j = 0; j < 4; j++)
                Ps[(c0 + j) * QS_STRIDE + r0 + i] = s[i][j];
        __syncthreads();

        // O += P @ V
#pragma unroll 16
        for (int kk = 0; kk < 64; kk++) {
            float a[4], bb[4];
#pragma unroll
            for (int i = 0; i < 4; i++) a[i]  = Ps[kk * QS_STRIDE + r0 + i];
#pragma unroll
            for (int j = 0; j < 4; j++) bb[j] = Vs[kk * VS_STRIDE + c0 + j];
#pragma unroll
            for (int i = 0; i < 4; i++)
#pragma unroll
                for (int j = 0; j < 4; j++)
                    o[i][j] += a[i] * bb[j];
        }
        __syncthreads();
    }

    // normalize + write z in [B,S,D] (heads concatenated)
#pragma unroll
    for (int i = 0; i < 4; i++) {
        float inv = 1.f / lrow[i];
        int gq = q0 + r0 + i;
        float* zp = g_z + ((size_t)b * Ssz + gq) * Dsz + h * HDsz + c0;
#pragma unroll
        for (int j = 0; j < 4; j++) zp[j] = o[i][j] * inv;
    }
}

// ---------------- launch ----------------

extern "C" void kernel_launch(void* const* d_in, const int* in_sizes, int n_in,
                              void* d_out, int out_size)
{
    (void)in_sizes; (void)n_in; (void)out_size;
    const float* X  = (const float*)d_in[0];
    const float* Wq = (const float*)d_in[1];
    const float* bq = (const float*)d_in[2];
    const float* Wk = (const float*)d_in[3];
    const float* bk = (const float*)d_in[4];
    const float* Wv = (const float*)d_in[5];
    const float* bv = (const float*)d_in[6];
    const float* Wo = (const float*)d_in[7];
    const float* bo = (const float*)d_in[8];
    float* out = (float*)d_out;

    cudaFuncSetAttribute(attn_kernel,
                         cudaFuncAttributeMaxDynamicSharedMemorySize, SMEM_BYTES);

    dim3 gProj(Dsz / BN, Msz / BM, 3);
    proj_kernel<<<gProj, 256>>>(X, Wq, bq, Wk, bk, Wv, bv);

    dim3 gAttn(Ssz / AQ, Hsz, Bsz);
    attn_kernel<<<gAttn, 256, SMEM_BYTES>>>();

    dim3 gOut(Dsz / BN, Msz / BM, 1);
    outproj_kernel<<<gOut, 256>>>(Wo, bo, out);
}

// round 2
// speedup vs baseline: 2.9167x; 2.9167x over previous
#include <cuda_runtime.h>
#include <cstdint>

#define Bsz 2
#define Ssz 2048
#define Dsz 1024
#define Hsz 16
#define HDsz 64
#define Msz (Bsz*Ssz)   // 4096

// scratch (allocation-free): q,k,v in [B,H,S,HD], z in [B,S,D]
__device__ __align__(16) float g_q[Bsz*Hsz*Ssz*HDsz];
__device__ __align__(16) float g_k[Bsz*Hsz*Ssz*HDsz];
__device__ __align__(16) float g_v[Bsz*Hsz*Ssz*HDsz];
__device__ __align__(16) float g_z[Msz*Dsz];

__device__ __forceinline__ uint32_t f2tf32(float x) {
    uint32_t u;
    asm("cvt.rna.tf32.f32 %0, %1;" : "=r"(u) : "f"(x));
    return u;
}

// mma.m16n8k8 row.col tf32, D += A*B (C aliased to D)
__device__ __forceinline__ void mma8(float* d, const uint32_t* a, const uint32_t* b) {
    asm volatile(
        "mma.sync.aligned.m16n8k8.row.col.f32.tf32.tf32.f32 "
        "{%0,%1,%2,%3}, {%4,%5,%6,%7}, {%8,%9}, {%0,%1,%2,%3};"
        : "+f"(d[0]), "+f"(d[1]), "+f"(d[2]), "+f"(d[3])
        : "r"(a[0]), "r"(a[1]), "r"(a[2]), "r"(a[3]), "r"(b[0]), "r"(b[1]));
}

// ================= tf32 MMA GEMM (NT): C[m,n] = A[m,:]·W[n,:] + bias[n] =================
// BM=BN=128, BK=16, 256 threads = 8 warps (2x4), warp tile 64x32 (4 m-frags x 4 n-frags).

#define BM 128
#define BN 128
#define BK 16
#define TS 20   // smem stride (conflict-free for frag reads)

template<int MODE>  // 0: scatter to [B,H,S,HD]; 1: row-major [M,D]
__device__ __forceinline__ void gemm_body(
    const float* __restrict__ A, const float* __restrict__ W,
    const float* __restrict__ bias, float* __restrict__ out,
    uint32_t* As, uint32_t* Bs)
{
    const int tid = threadIdx.x;
    const int lane = tid & 31, warp = tid >> 5;
    const int g = lane >> 2, cq = lane & 3;
    const int wm = warp >> 2, wn = warp & 3;
    const int m0 = blockIdx.y * BM, n0 = blockIdx.x * BN;

    float acc[4][4][4];
#pragma unroll
    for (int mi = 0; mi < 4; mi++)
#pragma unroll
        for (int nj = 0; nj < 4; nj++)
#pragma unroll
            for (int t = 0; t < 4; t++) acc[mi][nj][t] = 0.f;

    const float* Ap = A + (size_t)m0 * Dsz;
    const float* Wp = W + (size_t)n0 * Dsz;

    for (int k0 = 0; k0 < Dsz; k0 += BK) {
#pragma unroll
        for (int p = 0; p < 2; p++) {
            int idx = tid + p * 256;
            int row = idx >> 2, c4 = (idx & 3) << 2;
            float4 va = *(const float4*)(Ap + (size_t)row * Dsz + k0 + c4);
            uint4 ua = { f2tf32(va.x), f2tf32(va.y), f2tf32(va.z), f2tf32(va.w) };
            *(uint4*)(As + row * TS + c4) = ua;
            float4 vb = *(const float4*)(Wp + (size_t)row * Dsz + k0 + c4);
            uint4 ub = { f2tf32(vb.x), f2tf32(vb.y), f2tf32(vb.z), f2tf32(vb.w) };
            *(uint4*)(Bs + row * TS + c4) = ub;
        }
        __syncthreads();

#pragma unroll
        for (int kk = 0; kk < 2; kk++) {
            uint32_t af[4][4], bf[4][2];
#pragma unroll
            for (int mi = 0; mi < 4; mi++) {
                const uint32_t* p0 = As + (wm * 64 + mi * 16 + g) * TS + kk * 8 + cq;
                af[mi][0] = p0[0];
                af[mi][1] = p0[8 * TS];
                af[mi][2] = p0[4];
                af[mi][3] = p0[8 * TS + 4];
            }
#pragma unroll
            for (int nj = 0; nj < 4; nj++) {
                const uint32_t* p0 = Bs + (wn * 32 + nj * 8 + g) * TS + kk * 8 + cq;
                bf[nj][0] = p0[0];
                bf[nj][1] = p0[4];
            }
#pragma unroll
            for (int mi = 0; mi < 4; mi++)
#pragma unroll
                for (int nj = 0; nj < 4; nj++)
                    mma8(acc[mi][nj], af[mi], bf[nj]);
        }
        __syncthreads();
    }

    // epilogue: C layout rows = g, g+8; cols = 2*cq, 2*cq+1
#pragma unroll
    for (int mi = 0; mi < 4; mi++) {
        int m_lo = m0 + wm * 64 + mi * 16 + g;
        int m_hi = m_lo + 8;
#pragma unroll
        for (int nj = 0; nj < 4; nj++) {
            int n = n0 + wn * 32 + nj * 8 + 2 * cq;
            float b0 = bias[n], b1 = bias[n + 1];
            float2 lo = { acc[mi][nj][0] + b0, acc[mi][nj][1] + b1 };
            float2 hi = { acc[mi][nj][2] + b0, acc[mi][nj][3] + b1 };
            if (MODE == 0) {
                int h = n >> 6, e = n & 63;
                int bb = m_lo >> 11, s = m_lo & 2047;
                *(float2*)(out + (((size_t)(bb * Hsz + h) * Ssz) + s) * HDsz + e) = lo;
                bb = m_hi >> 11; s = m_hi & 2047;
                *(float2*)(out + (((size_t)(bb * Hsz + h) * Ssz) + s) * HDsz + e) = hi;
            } else {
                *(float2*)(out + (size_t)m_lo * Dsz + n) = lo;
                *(float2*)(out + (size_t)m_hi * Dsz + n) = hi;
            }
        }
    }
}

__global__ __launch_bounds__(256) void proj_kernel(
    const float* __restrict__ X,
    const float* __restrict__ Wq, const float* __restrict__ bq,
    const float* __restrict__ Wk, const float* __restrict__ bk,
    const float* __restrict__ Wv, const float* __restrict__ bv)
{
    __shared__ uint32_t As[BM * TS];
    __shared__ uint32_t Bs[BN * TS];
    const int which = blockIdx.z;
    const float* W    = (which == 0) ? Wq : (which == 1) ? Wk : Wv;
    const float* bias = (which == 0) ? bq : (which == 1) ? bk : bv;
    float* out        = (which == 0) ? g_q : (which == 1) ? g_k : g_v;
    gemm_body<0>(X, W, bias, out, As, Bs);
}

__global__ __launch_bounds__(256) void outproj_kernel(
    const float* __restrict__ Wo, const float* __restrict__ bo,
    float* __restrict__ out)
{
    __shared__ uint32_t As[BM * TS];
    __shared__ uint32_t Bs[BN * TS];
    gemm_body<1>(g_z, Wo, bo, out, As, Bs);
}

// ================= fused causal flash attention, tf32 MMA =================
// Block = 128 threads (4 warps), 64 Q rows per block; each warp owns 16 Q rows.
// K/V tiles of 64. Q fragments live in registers across the whole K loop.

#define AQT 64
#define KS_STR 68
#define VS_STR 72
#define PS_STR 68
#define ATT_SMEM_WORDS (64*KS_STR + 64*VS_STR + 64*PS_STR)
#define ATT_SMEM_BYTES (ATT_SMEM_WORDS * 4)   // 53248

__device__ __forceinline__ void stage_tile(
    const float* __restrict__ src, uint32_t* dst, int stride, int tid)
{
#pragma unroll
    for (int p = 0; p < 8; p++) {
        int idx = tid + p * 128;        // 0..1023
        int row = idx >> 4;             // 0..63
        int c4  = (idx & 15) << 2;      // 0..60
        float4 v = *(const float4*)(src + (size_t)row * HDsz + c4);
        uint4 u = { f2tf32(v.x), f2tf32(v.y), f2tf32(v.z), f2tf32(v.w) };
        *(uint4*)(dst + row * stride + c4) = u;
    }
}

__global__ __launch_bounds__(128) void attn_kernel()
{
    extern __shared__ uint32_t sm[];
    uint32_t* Ks = sm;                     // [64][KS_STR]
    uint32_t* Vs = Ks + 64 * KS_STR;       // [64][VS_STR]
    uint32_t* Ps = Vs + 64 * VS_STR;       // [64][PS_STR]

    const int tid = threadIdx.x;
    const int w = tid >> 5, lane = tid & 31;
    const int g = lane >> 2, cq = lane & 3;
    const int qt = gridDim.x - 1 - blockIdx.x;   // heavy tiles first
    const int q0 = qt * AQT;
    const int h = blockIdx.y, b = blockIdx.z;

    const size_t head_off = (size_t)(b * Hsz + h) * Ssz * HDsz;
    const float* Qp = g_q + head_off + (size_t)q0 * HDsz;
    const float* Kp = g_k + head_off;
    const float* Vp = g_v + head_off;

    // stage Q into Ks buffer, extract per-warp A fragments (8 k-steps x 4 regs)
    stage_tile(Qp, Ks, KS_STR, tid);
    __syncthreads();

    uint32_t qa[8][4];
    {
        const int r = w * 16 + g;
#pragma unroll
        for (int kk = 0; kk < 8; kk++) {
            const uint32_t* p0 = Ks + r * KS_STR + kk * 8 + cq;
            qa[kk][0] = p0[0];
            qa[kk][1] = p0[8 * KS_STR];
            qa[kk][2] = p0[4];
            qa[kk][3] = p0[8 * KS_STR + 4];
        }
    }

    float o[8][4];
#pragma unroll
    for (int nf = 0; nf < 8; nf++)
#pragma unroll
        for (int t = 0; t < 4; t++) o[nf][t] = 0.f;
    float m_lo = -1e30f, m_hi = -1e30f, l_lo = 0.f, l_hi = 0.f;

    const int nkt = qt + 1;
    const float scale = 0.125f;   // 1/sqrt(64)
    const int q_lo = q0 + w * 16 + g;
    const int q_hi = q_lo + 8;

    for (int jt = 0; jt < nkt; jt++) {
        const int k0 = jt * AQT;
        __syncthreads();   // previous tile fully consumed before refill
        stage_tile(Kp + (size_t)k0 * HDsz, Ks, KS_STR, tid);
        stage_tile(Vp + (size_t)k0 * HDsz, Vs, VS_STR, tid);
        __syncthreads();

        // S = Q @ K^T  (16 x 64 per warp)
        float s[8][4];
#pragma unroll
        for (int nf = 0; nf < 8; nf++)
#pragma unroll
            for (int t = 0; t < 4; t++) s[nf][t] = 0.f;

#pragma unroll
        for (int kk = 0; kk < 8; kk++) {
#pragma unroll
            for (int nf = 0; nf < 8; nf++) {
                const uint32_t* p0 = Ks + (nf * 8 + g) * KS_STR + kk * 8 + cq;
                uint32_t bf[2] = { p0[0], p0[4] };
                mma8(s[nf], qa[kk], bf);
            }
        }

        // scale + causal mask (only diagonal tile)
        const bool diag = (jt == nkt - 1);
#pragma unroll
        for (int nf = 0; nf < 8; nf++) {
            int n0c = k0 + nf * 8 + 2 * cq;
            s[nf][0] *= scale; s[nf][1] *= scale;
            s[nf][2] *= scale; s[nf][3] *= scale;
            if (diag) {
                if (n0c     > q_lo) s[nf][0] = -1e30f;
                if (n0c + 1 > q_lo) s[nf][1] = -1e30f;
                if (n0c     > q_hi) s[nf][2] = -1e30f;
                if (n0c + 1 > q_hi) s[nf][3] = -1e30f;
            }
        }

        // online softmax (row groups of 4 lanes: xor 1, 2)
        float mx0 = -1e30f, mx1 = -1e30f;
#pragma unroll
        for (int nf = 0; nf < 8; nf++) {
            mx0 = fmaxf(mx0, fmaxf(s[nf][0], s[nf][1]));
            mx1 = fmaxf(mx1, fmaxf(s[nf][2], s[nf][3]));
        }
        mx0 = fmaxf(mx0, __shfl_xor_sync(0xffffffffu, mx0, 1));
        mx0 = fmaxf(mx0, __shfl_xor_sync(0xffffffffu, mx0, 2));
        mx1 = fmaxf(mx1, __shfl_xor_sync(0xffffffffu, mx1, 1));
        mx1 = fmaxf(mx1, __shfl_xor_sync(0xffffffffu, mx1, 2));

        float mn0 = fmaxf(m_lo, mx0), mn1 = fmaxf(m_hi, mx1);
        float corr0 = __expf(m_lo - mn0), corr1 = __expf(m_hi - mn1);
        m_lo = mn0; m_hi = mn1;

        float sum0 = 0.f, sum1 = 0.f;
#pragma unroll
        for (int nf = 0; nf < 8; nf++) {
            s[nf][0] = __expf(s[nf][0] - mn0);
            s[nf][1] = __expf(s[nf][1] - mn0);
            s[nf][2] = __expf(s[nf][2] - mn1);
            s[nf][3] = __expf(s[nf][3] - mn1);
            sum0 += s[nf][0] + s[nf][1];
            sum1 += s[nf][2] + s[nf][3];
        }
        sum0 += __shfl_xor_sync(0xffffffffu, sum0, 1);
        sum0 += __shfl_xor_sync(0xffffffffu, sum0, 2);
        sum1 += __shfl_xor_sync(0xffffffffu, sum1, 1);
        sum1 += __shfl_xor_sync(0xffffffffu, sum1, 2);
        l_lo = l_lo * corr0 + sum0;
        l_hi = l_hi * corr1 + sum1;

#pragma unroll
        for (int nf = 0; nf < 8; nf++) {
            o[nf][0] *= corr0; o[nf][1] *= corr0;
            o[nf][2] *= corr1; o[nf][3] *= corr1;
        }

        // stage P (tf32) into warp-private smem rows, re-fragment as A
        {
            const int r = w * 16 + g;
#pragma unroll
            for (int nf = 0; nf < 8; nf++) {
                uint2 plo = { f2tf32(s[nf][0]), f2tf32(s[nf][1]) };
                uint2 phi = { f2tf32(s[nf][2]), f2tf32(s[nf][3]) };
                *(uint2*)(Ps + r * PS_STR + nf * 8 + 2 * cq) = plo;
                *(uint2*)(Ps + (r + 8) * PS_STR + nf * 8 + 2 * cq) = phi;
            }
        }
        __syncwarp();

        // O += P @ V
        {
            const int r = w * 16 + g;
#pragma unroll
            for (int kk = 0; kk < 8; kk++) {
                const uint32_t* p0 = Ps + r * PS_STR + kk * 8 + cq;
                uint32_t pa[4] = { p0[0], p0[8 * PS_STR], p0[4], p0[8 * PS_STR + 4] };
#pragma unroll
                for (int nf = 0; nf < 8; nf++) {
                    const uint32_t* v0 = Vs + (kk * 8 + cq) * VS_STR + nf * 8 + g;
                    uint32_t bf[2] = { v0[0], v0[4 * VS_STR] };
                    mma8(o[nf], pa, bf);
                }
            }
        }
        __syncwarp();
    }

    // normalize + write z [B,S,D]
    const float inv0 = 1.f / l_lo, inv1 = 1.f / l_hi;
    float* zlo = g_z + ((size_t)b * Ssz + q_lo) * Dsz + h * HDsz;
    float* zhi = g_z + ((size_t)b * Ssz + q_hi) * Dsz + h * HDsz;
#pragma unroll
    for (int nf = 0; nf < 8; nf++) {
        int cc = nf * 8 + 2 * cq;
        float2 lo = { o[nf][0] * inv0, o[nf][1] * inv0 };
        float2 hi = { o[nf][2] * inv1, o[nf][3] * inv1 };
        *(float2*)(zlo + cc) = lo;
        *(float2*)(zhi + cc) = hi;
    }
}

// ================= launch =================

extern "C" void kernel_launch(void* const* d_in, const int* in_sizes, int n_in,
                              void* d_out, int out_size)
{
    (void)in_sizes; (void)n_in; (void)out_size;
    const float* X  = (const float*)d_in[0];
    const float* Wq = (const float*)d_in[1];
    const float* bq = (const float*)d_in[2];
    const float* Wk = (const float*)d_in[3];
    const float* bk = (const float*)d_in[4];
    const float* Wv = (const float*)d_in[5];
    const float* bv = (const float*)d_in[6];
    const float* Wo = (const float*)d_in[7];
    const float* bo = (const float*)d_in[8];
    float* out = (float*)d_out;

    cudaFuncSetAttribute(attn_kernel,
                         cudaFuncAttributeMaxDynamicSharedMemorySize, ATT_SMEM_BYTES);

    dim3 gProj(Dsz / BN, Msz / BM, 3);
    proj_kernel<<<gProj, 256>>>(X, Wq, bq, Wk, bk, Wv, bv);

    dim3 gAttn(Ssz / AQT, Hsz, Bsz);
    attn_kernel<<<gAttn, 128, ATT_SMEM_BYTES>>>();

    dim3 gOut(Dsz / BN, Msz / BM, 1);
    outproj_kernel<<<gOut, 256>>>(Wo, bo, out);
}

// round 3
// speedup vs baseline: 3.1275x; 1.0723x over previous
#include <cuda_runtime.h>
#include <cstdint>

#define Bsz 2
#define Ssz 2048
#define Dsz 1024
#define Hsz 16
#define HDsz 64
#define Msz (Bsz*Ssz)   // 4096

// scratch (allocation-free): q,k,v in [B,H,S,HD], z in [B,S,D]
__device__ __align__(16) float g_q[Bsz*Hsz*Ssz*HDsz];
__device__ __align__(16) float g_k[Bsz*Hsz*Ssz*HDsz];
__device__ __align__(16) float g_v[Bsz*Hsz*Ssz*HDsz];
__device__ __align__(16) float g_z[Msz*Dsz];

__device__ __forceinline__ uint32_t f2tf32(float x) {
    uint32_t u;
    asm("cvt.rna.tf32.f32 %0, %1;" : "=r"(u) : "f"(x));
    return u;
}

// mma.m16n8k8 row.col tf32, D += A*B
__device__ __forceinline__ void mma8(float* d, const uint32_t* a, const uint32_t* b) {
    asm volatile(
        "mma.sync.aligned.m16n8k8.row.col.f32.tf32.tf32.f32 "
        "{%0,%1,%2,%3}, {%4,%5,%6,%7}, {%8,%9}, {%0,%1,%2,%3};"
        : "+f"(d[0]), "+f"(d[1]), "+f"(d[2]), "+f"(d[3])
        : "r"(a[0]), "r"(a[1]), "r"(a[2]), "r"(a[3]), "r"(b[0]), "r"(b[1]));
}

__device__ __forceinline__ void cp16(uint32_t smem_addr, const void* gptr) {
    asm volatile("cp.async.cg.shared.global [%0], [%1], 16;"
                 :: "r"(smem_addr), "l"(gptr));
}

// ================= pipelined tf32 MMA GEMM (NT) =================
// C[m,n] = A[m,:]·W[n,:] + bias[n].  BM=BN=128, BK=32, 256 thr = 8 warps (2x4),
// warp tile 64x32. Double-buffered smem fed by cp.async; cvt->tf32 at frag load.

#define BM 128
#define BN 128
#define BK 32
#define TSTR 36
#define GEMM_SMEM_WORDS (2 * 2 * 128 * TSTR)
#define GEMM_SMEM_BYTES (GEMM_SMEM_WORDS * 4)   // 73728

template<int MODE>  // 0: scatter to [B,H,S,HD]; 1: row-major [M,D]
__device__ __forceinline__ void gemm_body(
    const float* __restrict__ A, const float* __restrict__ W,
    const float* __restrict__ bias, float* __restrict__ out)
{
    extern __shared__ float smn[];
    float* As = smn;                       // [2][128][TSTR]
    float* Bs = smn + 2 * 128 * TSTR;      // [2][128][TSTR]

    const int tid = threadIdx.x;
    const int lane = tid & 31, warp = tid >> 5;
    const int g = lane >> 2, cq = lane & 3;
    const int wm = warp >> 2, wn = warp & 3;
    const int m0 = blockIdx.y * BM, n0 = blockIdx.x * BN;

    const float* Ap = A + (size_t)m0 * Dsz;
    const float* Wp = W + (size_t)n0 * Dsz;
    const uint32_t as_base = (uint32_t)__cvta_generic_to_shared(As);
    const uint32_t bs_base = (uint32_t)__cvta_generic_to_shared(Bs);

    float acc[4][4][4];
#pragma unroll
    for (int mi = 0; mi < 4; mi++)
#pragma unroll
        for (int nj = 0; nj < 4; nj++)
#pragma unroll
            for (int t = 0; t < 4; t++) acc[mi][nj][t] = 0.f;

    auto issue = [&](int buf, int k0) {
#pragma unroll
        for (int p = 0; p < 4; p++) {
            int idx = tid + p * 256;         // 0..1023
            int row = idx >> 3;              // 0..127
            int c4  = (idx & 7) << 2;        // 0..28
            uint32_t off = (uint32_t)(((buf * 128 + row) * TSTR + c4) * 4);
            cp16(as_base + off, Ap + (size_t)row * Dsz + k0 + c4);
            cp16(bs_base + off, Wp + (size_t)row * Dsz + k0 + c4);
        }
        asm volatile("cp.async.commit_group;");
    };

    issue(0, 0);

    const int T = Dsz / BK;   // 32
    for (int t = 0; t < T; t++) {
        if (t + 1 < T) {
            issue((t + 1) & 1, (t + 1) * BK);
            asm volatile("cp.async.wait_group 1;");
        } else {
            asm volatile("cp.async.wait_group 0;");
        }
        __syncthreads();

        const float* a_s = As + (t & 1) * 128 * TSTR;
        const float* b_s = Bs + (t & 1) * 128 * TSTR;
#pragma unroll
        for (int kk = 0; kk < 4; kk++) {
            uint32_t af[4][4], bf[4][2];
#pragma unroll
            for (int mi = 0; mi < 4; mi++) {
                const float* p0 = a_s + (wm * 64 + mi * 16 + g) * TSTR + kk * 8 + cq;
                af[mi][0] = f2tf32(p0[0]);
                af[mi][1] = f2tf32(p0[8 * TSTR]);
                af[mi][2] = f2tf32(p0[4]);
                af[mi][3] = f2tf32(p0[8 * TSTR + 4]);
            }
#pragma unroll
            for (int nj = 0; nj < 4; nj++) {
                const float* p0 = b_s + (wn * 32 + nj * 8 + g) * TSTR + kk * 8 + cq;
                bf[nj][0] = f2tf32(p0[0]);
                bf[nj][1] = f2tf32(p0[4]);
            }
#pragma unroll
            for (int mi = 0; mi < 4; mi++)
#pragma unroll
                for (int nj = 0; nj < 4; nj++)
                    mma8(acc[mi][nj], af[mi], bf[nj]);
        }
        __syncthreads();
    }

    // epilogue: rows = g, g+8; cols = 2*cq, 2*cq+1
#pragma unroll
    for (int mi = 0; mi < 4; mi++) {
        int m_lo = m0 + wm * 64 + mi * 16 + g;
        int m_hi = m_lo + 8;
#pragma unroll
        for (int nj = 0; nj < 4; nj++) {
            int n = n0 + wn * 32 + nj * 8 + 2 * cq;
            float b0 = bias[n], b1 = bias[n + 1];
            float2 lo = { acc[mi][nj][0] + b0, acc[mi][nj][1] + b1 };
            float2 hi = { acc[mi][nj][2] + b0, acc[mi][nj][3] + b1 };
            if (MODE == 0) {
                int h = n >> 6, e = n & 63;
                int bb = m_lo >> 11, s = m_lo & 2047;
                *(float2*)(out + (((size_t)(bb * Hsz + h) * Ssz) + s) * HDsz + e) = lo;
                bb = m_hi >> 11; s = m_hi & 2047;
                *(float2*)(out + (((size_t)(bb * Hsz + h) * Ssz) + s) * HDsz + e) = hi;
            } else {
                *(float2*)(out + (size_t)m_lo * Dsz + n) = lo;
                *(float2*)(out + (size_t)m_hi * Dsz + n) = hi;
            }
        }
    }
}

__global__ __launch_bounds__(256) void proj_kernel(
    const float* __restrict__ X,
    const float* __restrict__ Wq, const float* __restrict__ bq,
    const float* __restrict__ Wk, const float* __restrict__ bk,
    const float* __restrict__ Wv, const float* __restrict__ bv)
{
    const int which = blockIdx.z;
    const float* W    = (which == 0) ? Wq : (which == 1) ? Wk : Wv;
    const float* bias = (which == 0) ? bq : (which == 1) ? bk : bv;
    float* out        = (which == 0) ? g_q : (which == 1) ? g_k : g_v;
    gemm_body<0>(X, W, bias, out);
}

__global__ __launch_bounds__(256) void outproj_kernel(
    const float* __restrict__ Wo, const float* __restrict__ bo,
    float* __restrict__ out)
{
    gemm_body<1>(g_z, Wo, bo, out);
}

// ================= fused causal flash attention, tf32 MMA =================
// Block = 256 threads (8 warps), 128 Q rows per block; warp owns 16 Q rows.
// K/V tiles of 64 staged once per block -> 2x reuse vs 64-row blocks.

#define AQT 128
#define KS_STR 68
#define VS_STR 72
#define PS_STR 68
#define ATT_SMEM_WORDS (64*KS_STR + 64*VS_STR + 128*PS_STR)
#define ATT_SMEM_BYTES (ATT_SMEM_WORDS * 4)   // 70656

// stage ROWS x 64 fp32 tile -> tf32 uints in smem (256 threads)
template<int ROWS>
__device__ __forceinline__ void stage_tile(
    const float* __restrict__ src, uint32_t* dst, int stride, int tid)
{
#pragma unroll
    for (int p = 0; p < ROWS / 16; p++) {
        int idx = tid + p * 256;
        int row = idx >> 4;
        int c4  = (idx & 15) << 2;
        float4 v = *(const float4*)(src + (size_t)row * HDsz + c4);
        uint4 u = { f2tf32(v.x), f2tf32(v.y), f2tf32(v.z), f2tf32(v.w) };
        *(uint4*)(dst + row * stride + c4) = u;
    }
}

__global__ __launch_bounds__(256) void attn_kernel()
{
    extern __shared__ uint32_t sm[];
    uint32_t* Ks = sm;                     // [64][KS_STR]
    uint32_t* Vs = Ks + 64 * KS_STR;       // [64][VS_STR]
    uint32_t* Ps = Vs + 64 * VS_STR;       // [128][PS_STR]  (also Q staging)

    const int tid = threadIdx.x;
    const int w = tid >> 5, lane = tid & 31;
    const int g = lane >> 2, cq = lane & 3;
    const int qt = gridDim.x - 1 - blockIdx.x;   // heavy tiles first
    const int q0 = qt * AQT;
    const int h = blockIdx.y, b = blockIdx.z;

    const size_t head_off = (size_t)(b * Hsz + h) * Ssz * HDsz;
    const float* Qp = g_q + head_off + (size_t)q0 * HDsz;
    const float* Kp = g_k + head_off;
    const float* Vp = g_v + head_off;

    // stage Q (128 rows) into Ps, extract per-warp A fragments
    stage_tile<128>(Qp, Ps, PS_STR, tid);
    __syncthreads();

    uint32_t qa[8][4];
    {
        const int r = w * 16 + g;
#pragma unroll
        for (int kk = 0; kk < 8; kk++) {
            const uint32_t* p0 = Ps + r * PS_STR + kk * 8 + cq;
            qa[kk][0] = p0[0];
            qa[kk][1] = p0[8 * PS_STR];
            qa[kk][2] = p0[4];
            qa[kk][3] = p0[8 * PS_STR + 4];
        }
    }

    float o[8][4];
#pragma unroll
    for (int nf = 0; nf < 8; nf++)
#pragma unroll
        for (int t = 0; t < 4; t++) o[nf][t] = 0.f;
    float m_lo = -1e30f, m_hi = -1e30f, l_lo = 0.f, l_hi = 0.f;

    const int nkt = (q0 + AQT) / 64;       // K tiles needed for causal coverage
    const float scale = 0.125f;            // 1/sqrt(64)
    const int q_lo = q0 + w * 16 + g;
    const int q_hi = q_lo + 8;
    const int warp_min_row = q0 + w * 16;

    for (int jt = 0; jt < nkt; jt++) {
        const int k0 = jt * 64;
        __syncthreads();   // previous K/V fully consumed
        stage_tile<64>(Kp + (size_t)k0 * HDsz, Ks, KS_STR, tid);
        stage_tile<64>(Vp + (size_t)k0 * HDsz, Vs, VS_STR, tid);
        __syncthreads();

        // S = Q @ K^T  (16 x 64 per warp)
        float s[8][4];
#pragma unroll
        for (int nf = 0; nf < 8; nf++)
#pragma unroll
            for (int t = 0; t < 4; t++) s[nf][t] = 0.f;

#pragma unroll
        for (int kk = 0; kk < 8; kk++) {
#pragma unroll
            for (int nf = 0; nf < 8; nf++) {
                const uint32_t* p0 = Ks + (nf * 8 + g) * KS_STR + kk * 8 + cq;
                uint32_t bf[2] = { p0[0], p0[4] };
                mma8(s[nf], qa[kk], bf);
            }
        }

        // scale + causal mask (warp-uniform diag test)
        const bool diag = (k0 + 63 > warp_min_row);
#pragma unroll
        for (int nf = 0; nf < 8; nf++) {
            int n0c = k0 + nf * 8 + 2 * cq;
            s[nf][0] *= scale; s[nf][1] *= scale;
            s[nf][2] *= scale; s[nf][3] *= scale;
            if (diag) {
                if (n0c     > q_lo) s[nf][0] = -1e30f;
                if (n0c + 1 > q_lo) s[nf][1] = -1e30f;
                if (n0c     > q_hi) s[nf][2] = -1e30f;
                if (n0c + 1 > q_hi) s[nf][3] = -1e30f;
            }
        }

        // online softmax (row groups of 4 lanes: xor 1, 2)
        float mx0 = -1e30f, mx1 = -1e30f;
#pragma unroll
        for (int nf = 0; nf < 8; nf++) {
            mx0 = fmaxf(mx0, fmaxf(s[nf][0], s[nf][1]));
            mx1 = fmaxf(mx1, fmaxf(s[nf][2], s[nf][3]));
        }
        mx0 = fmaxf(mx0, __shfl_xor_sync(0xffffffffu, mx0, 1));
        mx0 = fmaxf(mx0, __shfl_xor_sync(0xffffffffu, mx0, 2));
        mx1 = fmaxf(mx1, __shfl_xor_sync(0xffffffffu, mx1, 1));
        mx1 = fmaxf(mx1, __shfl_xor_sync(0xffffffffu, mx1, 2));

        float mn0 = fmaxf(m_lo, mx0), mn1 = fmaxf(m_hi, mx1);
        float corr0 = __expf(m_lo - mn0), corr1 = __expf(m_hi - mn1);
        m_lo = mn0; m_hi = mn1;

        float sum0 = 0.f, sum1 = 0.f;
#pragma unroll
        for (int nf = 0; nf < 8; nf++) {
            s[nf][0] = __expf(s[nf][0] - mn0);
            s[nf][1] = __expf(s[nf][1] - mn0);
            s[nf][2] = __expf(s[nf][2] - mn1);
            s[nf][3] = __expf(s[nf][3] - mn1);
            sum0 += s[nf][0] + s[nf][1];
            sum1 += s[nf][2] + s[nf][3];
        }
        sum0 += __shfl_xor_sync(0xffffffffu, sum0, 1);
        sum0 += __shfl_xor_sync(0xffffffffu, sum0, 2);
        sum1 += __shfl_xor_sync(0xffffffffu, sum1, 1);
        sum1 += __shfl_xor_sync(0xffffffffu, sum1, 2);
        l_lo = l_lo * corr0 + sum0;
        l_hi = l_hi * corr1 + sum1;

#pragma unroll
        for (int nf = 0; nf < 8; nf++) {
            o[nf][0] *= corr0; o[nf][1] *= corr0;
            o[nf][2] *= corr1; o[nf][3] *= corr1;
        }

        // stage P (tf32) into warp-private smem rows, re-fragment as A
        {
            const int r = w * 16 + g;
#pragma unroll
            for (int nf = 0; nf < 8; nf++) {
                uint2 plo = { f2tf32(s[nf][0]), f2tf32(s[nf][1]) };
                uint2 phi = { f2tf32(s[nf][2]), f2tf32(s[nf][3]) };
                *(uint2*)(Ps + r * PS_STR + nf * 8 + 2 * cq) = plo;
                *(uint2*)(Ps + (r + 8) * PS_STR + nf * 8 + 2 * cq) = phi;
            }
        }
        __syncwarp();

        // O += P @ V
        {
            const int r = w * 16 + g;
#pragma unroll
            for (int kk = 0; kk < 8; kk++) {
                const uint32_t* p0 = Ps + r * PS_STR + kk * 8 + cq;
                uint32_t pa[4] = { p0[0], p0[8 * PS_STR], p0[4], p0[8 * PS_STR + 4] };
#pragma unroll
                for (int nf = 0; nf < 8; nf++) {
                    const uint32_t* v0 = Vs + (kk * 8 + cq) * VS_STR + nf * 8 + g;
                    uint32_t bf[2] = { v0[0], v0[4 * VS_STR] };
                    mma8(o[nf], pa, bf);
                }
            }
        }
        __syncwarp();
    }

    // normalize + write z [B,S,D]
    const float inv0 = 1.f / l_lo, inv1 = 1.f / l_hi;
    float* zlo = g_z + ((size_t)b * Ssz + q_lo) * Dsz + h * HDsz;
    float* zhi = g_z + ((size_t)b * Ssz + q_hi) * Dsz + h * HDsz;
#pragma unroll
    for (int nf = 0; nf < 8; nf++) {
        int cc = nf * 8 + 2 * cq;
        float2 lo = { o[nf][0] * inv0, o[nf][1] * inv0 };
        float2 hi = { o[nf][2] * inv1, o[nf][3] * inv1 };
        *(float2*)(zlo + cc) = lo;
        *(float2*)(zhi + cc) = hi;
    }
}

// ================= launch =================

extern "C" void kernel_launch(void* const* d_in, const int* in_sizes, int n_in,
                              void* d_out, int out_size)
{
    (void)in_sizes; (void)n_in; (void)out_size;
    const float* X  = (const float*)d_in[0];
    const float* Wq = (const float*)d_in[1];
    const float* bq = (const float*)d_in[2];
    const float* Wk = (const float*)d_in[3];
    const float* bk = (const float*)d_in[4];
    const float* Wv = (const float*)d_in[5];
    const float* bv = (const float*)d_in[6];
    const float* Wo = (const float*)d_in[7];
    const float* bo = (const float*)d_in[8];
    float* out = (float*)d_out;

    cudaFuncSetAttribute(proj_kernel,
                         cudaFuncAttributeMaxDynamicSharedMemorySize, GEMM_SMEM_BYTES);
    cudaFuncSetAttribute(outproj_kernel,
                         cudaFuncAttributeMaxDynamicSharedMemorySize, GEMM_SMEM_BYTES);
    cudaFuncSetAttribute(attn_kernel,
                         cudaFuncAttributeMaxDynamicSharedMemorySize, ATT_SMEM_BYTES);

    dim3 gProj(Dsz / BN, Msz / BM, 3);
    proj_kernel<<<gProj, 256, GEMM_SMEM_BYTES>>>(X, Wq, bq, Wk, bk, Wv, bv);

    dim3 gAttn(Ssz / AQT, Hsz, Bsz);
    attn_kernel<<<gAttn, 256, ATT_SMEM_BYTES>>>();

    dim3 gOut(Dsz / BN, Msz / BM, 1);
    outproj_kernel<<<gOut, 256, GEMM_SMEM_BYTES>>>(Wo, bo, out);
}

// round 5
// speedup vs baseline: 5.8843x; 1.8815x over previous
#include <cuda_runtime.h>
#include <cuda_fp16.h>
#include <cstdint>

#define Bsz 2
#define Ssz 2048
#define Dsz 1024
#define Hsz 16
#define HDsz 64
#define Msz (Bsz*Ssz)   // 4096

// fp16 scratch (allocation-free)
__device__ __align__(16) __half g_xh[Msz*Dsz];        // X rounded
__device__ __align__(16) __half g_wh[4*Dsz*Dsz];      // Wq,Wk,Wv,Wo rounded
__device__ __align__(16) __half g_q[Bsz*Hsz*Ssz*HDsz];   // [B,H,S,HD]
__device__ __align__(16) __half g_k[Bsz*Hsz*Ssz*HDsz];   // [B,H,S,HD]
__device__ __align__(16) __half g_v[Bsz*Hsz*Ssz*HDsz];   // [B,H,HD,S]  (transposed!)
__device__ __align__(16) __half g_zh[Msz*Dsz];        // attention output

// ---------------- helpers ----------------

__device__ __forceinline__ void cp16(uint32_t smem_addr, const void* gptr) {
    asm volatile("cp.async.cg.shared.global [%0], [%1], 16;"
                 :: "r"(smem_addr), "l"(gptr));
}

// mma.m16n8k16 row.col f16 -> f32, D += A*B
__device__ __forceinline__ void mma16(float* d, const uint32_t* a, uint32_t b0, uint32_t b1) {
    asm volatile(
        "mma.sync.aligned.m16n8k16.row.col.f32.f16.f16.f32 "
        "{%0,%1,%2,%3}, {%4,%5,%6,%7}, {%8,%9}, {%0,%1,%2,%3};"
        : "+f"(d[0]), "+f"(d[1]), "+f"(d[2]), "+f"(d[3])
        : "r"(a[0]), "r"(a[1]), "r"(a[2]), "r"(a[3]), "r"(b0), "r"(b1));
}

__device__ __forceinline__ uint32_t packh2(float lo, float hi) {
    half2 h = __floats2half2_rn(lo, hi);
    return *(uint32_t*)&h;
}

// ---------------- pre-round: fp32 -> fp16 scratch ----------------

__global__ __launch_bounds__(256) void preround_kernel(
    const float* __restrict__ X, const float* __restrict__ Wq,
    const float* __restrict__ Wk, const float* __restrict__ Wv,
    const float* __restrict__ Wo)
{
    const int z = blockIdx.z;
    const float* src;
    __half* dst;
    int iters;
    if (z == 0) { src = X; dst = g_xh; iters = 4; }
    else {
        src = (z == 1) ? Wq : (z == 2) ? Wk : (z == 3) ? Wv : Wo;
        dst = g_wh + (size_t)(z - 1) * Dsz * Dsz;
        iters = 1;
    }
#pragma unroll
    for (int it = 0; it < 4; it++) {
        if (it >= iters) break;
        size_t i = (size_t)(blockIdx.x * 256 + threadIdx.x) + (size_t)it * (1024 * 256);
        float4 v = ((const float4*)src)[i];
        half2* d2 = (half2*)dst;
        d2[2 * i]     = __floats2half2_rn(v.x, v.y);
        d2[2 * i + 1] = __floats2half2_rn(v.z, v.w);
    }
}

// ================= fp16 MMA GEMM (NT): C[m,n] = A[m,:]·W[n,:] + bias[n] =================
// 128x128 tile, BK=64 (halves), double-buffered cp.async, 256 thr = 8 warps (2x4),
// warp tile 64x32, m16n8k16.

#define SROW 36                    // 32-bit words per 64-half row (32 + 4 pad)
#define GBUF (128 * SROW)          // words per buffer per matrix
#define GEMM_SMEM_BYTES (4 * GBUF * 4)   // 73728

// MODE 0: scatter to half [B,H,S,HD]; 1: V transposed half [B,H,HD,S]; 2: fp32 [M,D]
template<int MODE>
__device__ __forceinline__ void gemm_body(
    const __half* __restrict__ A, const __half* __restrict__ W,
    const float* __restrict__ bias, void* __restrict__ outp)
{
    extern __shared__ uint32_t smw[];
    const int tid = threadIdx.x;
    const int lane = tid & 31, warp = tid >> 5;
    const int g = lane >> 2, cq = lane & 3;
    const int wm = warp >> 2, wn = warp & 3;
    const int m0 = blockIdx.y * 128, n0 = blockIdx.x * 128;

    const __half* Ap = A + (size_t)m0 * Dsz;
    const __half* Wp = W + (size_t)n0 * Dsz;
    const uint32_t sbase = (uint32_t)__cvta_generic_to_shared(smw);

    float acc[4][4][4];
#pragma unroll
    for (int mi = 0; mi < 4; mi++)
#pragma unroll
        for (int nj = 0; nj < 4; nj++)
#pragma unroll
            for (int t = 0; t < 4; t++) acc[mi][nj][t] = 0.f;

    auto issue = [&](int buf, int k0) {
#pragma unroll
        for (int p = 0; p < 4; p++) {
            int idx = tid + p * 256;          // 0..1023
            int row = idx >> 3;               // 0..127
            int c   = idx & 7;                // 16B chunk
            uint32_t off = (uint32_t)((buf * GBUF + row * SROW + c * 4) * 4);
            cp16(sbase + off,                Ap + (size_t)row * Dsz + k0 + c * 8);
            cp16(sbase + off + 2 * GBUF * 4, Wp + (size_t)row * Dsz + k0 + c * 8);
        }
        asm volatile("cp.async.commit_group;");
    };

    issue(0, 0);

    const int T = Dsz / 64;   // 16
    for (int t = 0; t < T; t++) {
        if (t + 1 < T) {
            issue((t + 1) & 1, (t + 1) * 64);
            asm volatile("cp.async.wait_group 1;");
        } else {
            asm volatile("cp.async.wait_group 0;");
        }
        __syncthreads();

        const uint32_t* a_s = smw + (t & 1) * GBUF;
        const uint32_t* b_s = smw + 2 * GBUF + (t & 1) * GBUF;
#pragma unroll
        for (int kk = 0; kk < 4; kk++) {
            uint32_t af[4][4], bf[4][2];
#pragma unroll
            for (int mi = 0; mi < 4; mi++) {
                const uint32_t* p0 = a_s + (wm * 64 + mi * 16 + g) * SROW + kk * 8 + cq;
                af[mi][0] = p0[0];
                af[mi][1] = p0[8 * SROW];
                af[mi][2] = p0[4];
                af[mi][3] = p0[8 * SROW + 4];
            }
#pragma unroll
            for (int nj = 0; nj < 4; nj++) {
                const uint32_t* p0 = b_s + (wn * 32 + nj * 8 + g) * SROW + kk * 8 + cq;
                bf[nj][0] = p0[0];
                bf[nj][1] = p0[4];
            }
#pragma unroll
            for (int mi = 0; mi < 4; mi++)
#pragma unroll
                for (int nj = 0; nj < 4; nj++)
                    mma16(acc[mi][nj], af[mi], bf[nj][0], bf[nj][1]);
        }
        __syncthreads();
    }

    // epilogue: rows g, g+8; cols 2cq, 2cq+1
#pragma unroll
    for (int mi = 0; mi < 4; mi++) {
        int m_lo = m0 + wm * 64 + mi * 16 + g;
        int m_hi = m_lo + 8;
#pragma unroll
        for (int nj = 0; nj < 4; nj++) {
            int n = n0 + wn * 32 + nj * 8 + 2 * cq;
            float b0 = bias[n], b1 = bias[n + 1];
            float v00 = acc[mi][nj][0] + b0, v01 = acc[mi][nj][1] + b1;
            float v10 = acc[mi][nj][2] + b0, v11 = acc[mi][nj][3] + b1;
            if (MODE == 0) {
                __half* out = (__half*)outp;
                int h = n >> 6, e = n & 63;
                int bb = m_lo >> 11, s = m_lo & 2047;
                *(half2*)(out + (((size_t)(bb * Hsz + h) * Ssz) + s) * HDsz + e) =
                    __floats2half2_rn(v00, v01);
                bb = m_hi >> 11; s = m_hi & 2047;
                *(half2*)(out + (((size_t)(bb * Hsz + h) * Ssz) + s) * HDsz + e) =
                    __floats2half2_rn(v10, v11);
            } else if (MODE == 1) {
                __half* out = (__half*)outp;
                int h = n >> 6, e = n & 63;
                int bb = m_lo >> 11, s = m_lo & 2047;
                size_t base = ((size_t)(bb * Hsz + h) * HDsz + e) * Ssz + s;
                out[base]       = __float2half_rn(v00);
                out[base + Ssz] = __float2half_rn(v01);
                bb = m_hi >> 11; s = m_hi & 2047;
                base = ((size_t)(bb * Hsz + h) * HDsz + e) * Ssz + s;
                out[base]       = __float2half_rn(v10);
                out[base + Ssz] = __float2half_rn(v11);
            } else {
                float* out = (float*)outp;
                *(float2*)(out + (size_t)m_lo * Dsz + n) = make_float2(v00, v01);
                *(float2*)(out + (size_t)m_hi * Dsz + n) = make_float2(v10, v11);
            }
        }
    }
}

__global__ __launch_bounds__(256) void proj_qk_kernel(
    const float* __restrict__ bq, const float* __restrict__ bk)
{
    const int which = blockIdx.z;
    const __half* W   = g_wh + (size_t)which * Dsz * Dsz;
    const float* bias = (which == 0) ? bq : bk;
    __half* out       = (which == 0) ? g_q : g_k;
    gemm_body<0>(g_xh, W, bias, out);
}

__global__ __launch_bounds__(256) void proj_v_kernel(const float* __restrict__ bv)
{
    gemm_body<1>(g_xh, g_wh + 2 * (size_t)Dsz * Dsz, bv, g_v);
}

__global__ __launch_bounds__(256) void outproj_kernel(
    const float* __restrict__ bo, float* __restrict__ out)
{
    gemm_body<2>(g_zh, g_wh + 3 * (size_t)Dsz * Dsz, bo, out);
}

// ================= fused causal flash attention, fp16 m16n8k16 =================
// 256 thr = 8 warps, 128 Q rows/block (16 per warp). K/V tiles of 64, cp.async
// double-buffered. P stays in registers (C-frag -> A-frag packing).

#define AQT 128
#define QOFF 0
#define QWORDS (128 * SROW)          // 4608
#define KOFF QWORDS
#define KBUF (64 * SROW)             // 2304
#define VOFF (KOFF + 2 * KBUF)
#define ATT_SMEM_WORDS (QWORDS + 4 * KBUF)
#define ATT_SMEM_BYTES (ATT_SMEM_WORDS * 4)   // 55296

__global__ __launch_bounds__(256) void attn_kernel()
{
    extern __shared__ uint32_t smw[];
    const uint32_t sbase = (uint32_t)__cvta_generic_to_shared(smw);

    const int tid = threadIdx.x;
    const int w = tid >> 5, lane = tid & 31;
    const int g = lane >> 2, cq = lane & 3;
    const int qt = gridDim.x - 1 - blockIdx.x;   // heavy tiles first
    const int q0 = qt * AQT;
    const int h = blockIdx.y, b = blockIdx.z;

    const size_t bh = (size_t)(b * Hsz + h);
    const __half* Qp = g_q + (bh * Ssz + q0) * HDsz;
    const __half* Kp = g_k + bh * Ssz * HDsz;
    const __half* Vp = g_v + bh * HDsz * Ssz;    // [HD][S]

    auto issueK = [&](int buf, int k0) {
#pragma unroll
        for (int p = 0; p < 2; p++) {
            int idx = tid + p * 256;    // 0..511
            int row = idx >> 3;         // seq row 0..63
            int c   = idx & 7;
            uint32_t off = (uint32_t)((KOFF + buf * KBUF + row * SROW + c * 4) * 4);
            cp16(sbase + off, Kp + ((size_t)(k0 + row)) * HDsz + c * 8);
        }
    };
    auto issueV = [&](int buf, int k0) {
#pragma unroll
        for (int p = 0; p < 2; p++) {
            int idx = tid + p * 256;
            int row = idx >> 3;         // hd row 0..63
            int c   = idx & 7;
            uint32_t off = (uint32_t)((VOFF + buf * KBUF + row * SROW + c * 4) * 4);
            cp16(sbase + off, Vp + (size_t)row * Ssz + k0 + c * 8);
        }
    };

    // group 0: Q + K0 + V0
    {
#pragma unroll
        for (int p = 0; p < 4; p++) {
            int idx = tid + p * 256;    // 0..1023
            int row = idx >> 3;         // 0..127
            int c   = idx & 7;
            uint32_t off = (uint32_t)((QOFF + row * SROW + c * 4) * 4);
            cp16(sbase + off, Qp + (size_t)row * HDsz + c * 8);
        }
        issueK(0, 0);
        issueV(0, 0);
        asm volatile("cp.async.commit_group;");
    }

    float o[8][4];
#pragma unroll
    for (int nf = 0; nf < 8; nf++)
#pragma unroll
        for (int t = 0; t < 4; t++) o[nf][t] = 0.f;
    float m_lo = -1e30f, m_hi = -1e30f, l_lo = 0.f, l_hi = 0.f;

    uint32_t qa[4][4];
    const int nkt = (q0 + AQT) / 64;
    const float scale = 0.125f;   // 1/sqrt(64)
    const int q_lo = q0 + w * 16 + g;
    const int q_hi = q_lo + 8;
    const int warp_min_row = q0 + w * 16;

    for (int jt = 0; jt < nkt; jt++) {
        const int k0 = jt * 64;
        const int buf = jt & 1;
        if (jt + 1 < nkt) {
            issueK(buf ^ 1, k0 + 64);
            issueV(buf ^ 1, k0 + 64);
            asm volatile("cp.async.commit_group;");
            asm volatile("cp.async.wait_group 1;");
        } else {
            asm volatile("cp.async.wait_group 0;");
        }
        __syncthreads();

        if (jt == 0) {
            // extract Q A-fragments (once)
            const int r = w * 16 + g;
#pragma unroll
            for (int kk = 0; kk < 4; kk++) {
                const uint32_t* p0 = smw + QOFF + r * SROW + kk * 8 + cq;
                qa[kk][0] = p0[0];
                qa[kk][1] = p0[8 * SROW];
                qa[kk][2] = p0[4];
                qa[kk][3] = p0[8 * SROW + 4];
            }
        }

        // S = Q @ K^T  (16 x 64 per warp)
        float s[8][4];
#pragma unroll
        for (int nf = 0; nf < 8; nf++)
#pragma unroll
            for (int t = 0; t < 4; t++) s[nf][t] = 0.f;

        const uint32_t* ksb = smw + KOFF + buf * KBUF;
#pragma unroll
        for (int kk = 0; kk < 4; kk++) {
#pragma unroll
            for (int nf = 0; nf < 8; nf++) {
                const uint32_t* p0 = ksb + (nf * 8 + g) * SROW + kk * 8 + cq;
                mma16(s[nf], qa[kk], p0[0], p0[4]);
            }
        }

        // scale + causal mask
        const bool diag = (k0 + 63 > warp_min_row);
#pragma unroll
        for (int nf = 0; nf < 8; nf++) {
            int n0c = k0 + nf * 8 + 2 * cq;
            s[nf][0] *= scale; s[nf][1] *= scale;
            s[nf][2] *= scale; s[nf][3] *= scale;
            if (diag) {
                if (n0c     > q_lo) s[nf][0] = -1e30f;
                if (n0c + 1 > q_lo) s[nf][1] = -1e30f;
                if (n0c     > q_hi) s[nf][2] = -1e30f;
                if (n0c + 1 > q_hi) s[nf][3] = -1e30f;
            }
        }

        // online softmax (row groups of 4 lanes)
        float mx0 = -1e30f, mx1 = -1e30f;
#pragma unroll
        for (int nf = 0; nf < 8; nf++) {
            mx0 = fmaxf(mx0, fmaxf(s[nf][0], s[nf][1]));
            mx1 = fmaxf(mx1, fmaxf(s[nf][2], s[nf][3]));
        }
        mx0 = fmaxf(mx0, __shfl_xor_sync(0xffffffffu, mx0, 1));
        mx0 = fmaxf(mx0, __shfl_xor_sync(0xffffffffu, mx0, 2));
        mx1 = fmaxf(mx1, __shfl_xor_sync(0xffffffffu, mx1, 1));
        mx1 = fmaxf(mx1, __shfl_xor_sync(0xffffffffu, mx1, 2));

        float mn0 = fmaxf(m_lo, mx0), mn1 = fmaxf(m_hi, mx1);
        float corr0 = __expf(m_lo - mn0), corr1 = __expf(m_hi - mn1);
        m_lo = mn0; m_hi = mn1;

        float sum0 = 0.f, sum1 = 0.f;
#pragma unroll
        for (int nf = 0; nf < 8; nf++) {
            s[nf][0] = __expf(s[nf][0] - mn0);
            s[nf][1] = __expf(s[nf][1] - mn0);
            s[nf][2] = __expf(s[nf][2] - mn1);
            s[nf][3] = __expf(s[nf][3] - mn1);
            sum0 += s[nf][0] + s[nf][1];
            sum1 += s[nf][2] + s[nf][3];
        }
        sum0 += __shfl_xor_sync(0xffffffffu, sum0, 1);
        sum0 += __shfl_xor_sync(0xffffffffu, sum0, 2);
        sum1 += __shfl_xor_sync(0xffffffffu, sum1, 1);
        sum1 += __shfl_xor_sync(0xffffffffu, sum1, 2);
        l_lo = l_lo * corr0 + sum0;
        l_hi = l_hi * corr1 + sum1;

#pragma unroll
        for (int nf = 0; nf < 8; nf++) {
            o[nf][0] *= corr0; o[nf][1] *= corr0;
            o[nf][2] *= corr1; o[nf][3] *= corr1;
        }

        // O += P @ V : P C-frags -> A-frags by register packing (no smem!)
        const uint32_t* vsb = smw + VOFF + buf * KBUF;
#pragma unroll
        for (int kk = 0; kk < 4; kk++) {
            uint32_t pa[4];
            pa[0] = packh2(s[2 * kk][0],     s[2 * kk][1]);
            pa[1] = packh2(s[2 * kk][2],     s[2 * kk][3]);
            pa[2] = packh2(s[2 * kk + 1][0], s[2 * kk + 1][1]);
            pa[3] = packh2(s[2 * kk + 1][2], s[2 * kk + 1][3]);
#pragma unroll
            for (int nf = 0; nf < 8; nf++) {
                const uint32_t* v0 = vsb + (nf * 8 + g) * SROW + kk * 8 + cq;
                mma16(o[nf], pa, v0[0], v0[4]);
            }
        }
        __syncthreads();   // tile consumed; safe to refill this buffer
    }

    // normalize + write z (fp16) [B,S,D]
    const float inv0 = 1.f / l_lo, inv1 = 1.f / l_hi;
    __half* zlo = g_zh + ((size_t)b * Ssz + q_lo) * Dsz + h * HDsz;
    __half* zhi = g_zh + ((size_t)b * Ssz + q_hi) * Dsz + h * HDsz;
#pragma unroll
    for (int nf = 0; nf < 8; nf++) {
        int cc = nf * 8 + 2 * cq;
        *(half2*)(zlo + cc) = __floats2half2_rn(o[nf][0] * inv0, o[nf][1] * inv0);
        *(half2*)(zhi + cc) = __floats2half2_rn(o[nf][2] * inv1, o[nf][3] * inv1);
    }
}

// ================= launch =================

extern "C" void kernel_launch(void* const* d_in, const int* in_sizes, int n_in,
                              void* d_out, int out_size)
{
    (void)in_sizes; (void)n_in; (void)out_size;
    const float* X  = (const float*)d_in[0];
    const float* Wq = (const float*)d_in[1];
    const float* bq = (const float*)d_in[2];
    const float* Wk = (const float*)d_in[3];
    const float* bk = (const float*)d_in[4];
    const float* Wv = (const float*)d_in[5];
    const float* bv = (const float*)d_in[6];
    const float* Wo = (const float*)d_in[7];
    const float* bo = (const float*)d_in[8];
    float* out = (float*)d_out;

    cudaFuncSetAttribute(proj_qk_kernel,
                         cudaFuncAttributeMaxDynamicSharedMemorySize, GEMM_SMEM_BYTES);
    cudaFuncSetAttribute(proj_v_kernel,
                         cudaFuncAttributeMaxDynamicSharedMemorySize, GEMM_SMEM_BYTES);
    cudaFuncSetAttribute(outproj_kernel,
                         cudaFuncAttributeMaxDynamicSharedMemorySize, GEMM_SMEM_BYTES);
    cudaFuncSetAttribute(attn_kernel,
                         cudaFuncAttributeMaxDynamicSharedMemorySize, ATT_SMEM_BYTES);

    preround_kernel<<<dim3(1024, 1, 5), 256>>>(X, Wq, Wk, Wv, Wo);

    proj_qk_kernel<<<dim3(Dsz / 128, Msz / 128, 2), 256, GEMM_SMEM_BYTES>>>(bq, bk);
    proj_v_kernel<<<dim3(Dsz / 128, Msz / 128, 1), 256, GEMM_SMEM_BYTES>>>(bv);

    attn_kernel<<<dim3(Ssz / AQT, Hsz, Bsz), 256, ATT_SMEM_BYTES>>>();

    outproj_kernel<<<dim3(Dsz / 128, Msz / 128, 1), 256, GEMM_SMEM_BYTES>>>(bo, out);
}

// round 6
// speedup vs baseline: 6.5995x; 1.1215x over previous
#include <cuda_runtime.h>
#include <cuda_fp16.h>
#include <cstdint>

#define Bsz 2
#define Ssz 2048
#define Dsz 1024
#define Hsz 16
#define HDsz 64
#define Msz (Bsz*Ssz)   // 4096

#define QSCALE 0.18033688011112042f   // 0.125 * log2(e)
#define ONE2 0x3C003C00u              // half2(1,1)

// fp16 scratch (allocation-free)
__device__ __align__(16) __half g_xh[Msz*Dsz];
__device__ __align__(16) __half g_wh[4*Dsz*Dsz];       // Wq(pre-scaled),Wk,Wv,Wo
__device__ __align__(16) __half g_q[Bsz*Hsz*Ssz*HDsz]; // [B,H,S,HD]
__device__ __align__(16) __half g_k[Bsz*Hsz*Ssz*HDsz]; // [B,H,S,HD]
__device__ __align__(16) __half g_v[Bsz*Hsz*Ssz*HDsz]; // [B,H,HD,S] (transposed)
__device__ __align__(16) __half g_zh[Msz*Dsz];

// ---------------- helpers ----------------

__device__ __forceinline__ void cp16(uint32_t smem_addr, const void* gptr) {
    asm volatile("cp.async.cg.shared.global [%0], [%1], 16;"
                 :: "r"(smem_addr), "l"(gptr));
}

__device__ __forceinline__ void mma16(float* d, const uint32_t* a, uint32_t b0, uint32_t b1) {
    asm volatile(
        "mma.sync.aligned.m16n8k16.row.col.f32.f16.f16.f32 "
        "{%0,%1,%2,%3}, {%4,%5,%6,%7}, {%8,%9}, {%0,%1,%2,%3};"
        : "+f"(d[0]), "+f"(d[1]), "+f"(d[2]), "+f"(d[3])
        : "r"(a[0]), "r"(a[1]), "r"(a[2]), "r"(a[3]), "r"(b0), "r"(b1));
}

__device__ __forceinline__ void ldsm4(uint32_t* r, uint32_t addr) {
    asm volatile("ldmatrix.sync.aligned.m8n8.x4.shared.b16 {%0,%1,%2,%3}, [%4];"
                 : "=r"(r[0]), "=r"(r[1]), "=r"(r[2]), "=r"(r[3]) : "r"(addr));
}

__device__ __forceinline__ uint32_t packh2(float lo, float hi) {
    half2 h = __floats2half2_rn(lo, hi);
    return *(uint32_t*)&h;
}

__device__ __forceinline__ float ex2f(float x) {
    float y;
    asm("ex2.approx.ftz.f32 %0, %1;" : "=f"(y) : "f"(x));
    return y;
}

__device__ __forceinline__ uint32_t h2ex2(uint32_t x) {
    uint32_t y;
    asm("ex2.approx.f16x2 %0, %1;" : "=r"(y) : "r"(x));
    return y;
}

// ---------------- pre-round: fp32 -> fp16 (Wq scaled by QSCALE) ----------------

__global__ __launch_bounds__(256) void preround_kernel(
    const float* __restrict__ X, const float* __restrict__ Wq,
    const float* __restrict__ Wk, const float* __restrict__ Wv,
    const float* __restrict__ Wo)
{
    const int z = blockIdx.z;
    const float* src;
    __half* dst;
    int iters;
    float sc = 1.0f;
    if (z == 0) { src = X; dst = g_xh; iters = 4; }
    else {
        src = (z == 1) ? Wq : (z == 2) ? Wk : (z == 3) ? Wv : Wo;
        dst = g_wh + (size_t)(z - 1) * Dsz * Dsz;
        iters = 1;
        if (z == 1) sc = QSCALE;
    }
#pragma unroll
    for (int it = 0; it < 4; it++) {
        if (it >= iters) break;
        size_t i = (size_t)(blockIdx.x * 256 + threadIdx.x) + (size_t)it * (1024 * 256);
        float4 v = ((const float4*)src)[i];
        half2* d2 = (half2*)dst;
        d2[2 * i]     = __floats2half2_rn(v.x * sc, v.y * sc);
        d2[2 * i + 1] = __floats2half2_rn(v.z * sc, v.w * sc);
    }
}

// ================= fp16 MMA GEMM (NT), ldmatrix fragment loads =================
// 128x128 tile, BK=64, double-buffered cp.async, 256 thr = 8 warps (2x4).

#define SROW 36                    // 32-bit words per 64-half row (32 + 4 pad)
#define GBUF (128 * SROW)
#define GEMM_SMEM_BYTES (4 * GBUF * 4)   // 73728

// MODE 0: half [B,H,S,HD]; 1: V transposed half [B,H,HD,S]; 2: fp32 [M,D]
template<int MODE>
__device__ __forceinline__ void gemm_body(
    const __half* __restrict__ A, const __half* __restrict__ W,
    const float* __restrict__ bias, float bscale, void* __restrict__ outp)
{
    extern __shared__ uint32_t smw[];
    const int tid = threadIdx.x;
    const int lane = tid & 31, warp = tid >> 5;
    const int g = lane >> 2, cq = lane & 3;
    const int wm = warp >> 2, wn = warp & 3;
    const int m0 = blockIdx.y * 128, n0 = blockIdx.x * 128;

    const __half* Ap = A + (size_t)m0 * Dsz;
    const __half* Wp = W + (size_t)n0 * Dsz;
    const uint32_t sbase = (uint32_t)__cvta_generic_to_shared(smw);

    // ldmatrix per-lane byte offsets
    const uint32_t offA = (uint32_t)(((lane & 7) + 8 * ((lane >> 3) & 1)) * SROW * 4
                                     + (lane >> 4) * 16);
    const uint32_t offB = (uint32_t)(((lane & 7) + 8 * (lane >> 4)) * SROW * 4
                                     + ((lane >> 3) & 1) * 16);

    float acc[4][4][4];
#pragma unroll
    for (int mi = 0; mi < 4; mi++)
#pragma unroll
        for (int nj = 0; nj < 4; nj++)
#pragma unroll
            for (int t = 0; t < 4; t++) acc[mi][nj][t] = 0.f;

    auto issue = [&](int buf, int k0) {
#pragma unroll
        for (int p = 0; p < 4; p++) {
            int idx = tid + p * 256;
            int row = idx >> 3;
            int c   = idx & 7;
            uint32_t off = (uint32_t)((buf * GBUF + row * SROW + c * 4) * 4);
            cp16(sbase + off,                Ap + (size_t)row * Dsz + k0 + c * 8);
            cp16(sbase + off + 2 * GBUF * 4, Wp + (size_t)row * Dsz + k0 + c * 8);
        }
        asm volatile("cp.async.commit_group;");
    };

    issue(0, 0);

    const int T = Dsz / 64;
    for (int t = 0; t < T; t++) {
        if (t + 1 < T) {
            issue((t + 1) & 1, (t + 1) * 64);
            asm volatile("cp.async.wait_group 1;");
        } else {
            asm volatile("cp.async.wait_group 0;");
        }
        __syncthreads();

        const uint32_t aBuf = sbase + (uint32_t)((t & 1) * GBUF * 4);
        const uint32_t bBuf = sbase + (uint32_t)((2 + (t & 1)) * GBUF * 4);
#pragma unroll
        for (int kk = 0; kk < 4; kk++) {
            uint32_t af[4][4], bf[2][4];
#pragma unroll
            for (int mi = 0; mi < 4; mi++)
                ldsm4(af[mi], aBuf + (uint32_t)((wm * 64 + mi * 16) * SROW * 4 + kk * 32) + offA);
#pragma unroll
            for (int p = 0; p < 2; p++)
                ldsm4(bf[p], bBuf + (uint32_t)((wn * 32 + p * 16) * SROW * 4 + kk * 32) + offB);
#pragma unroll
            for (int mi = 0; mi < 4; mi++)
#pragma unroll
                for (int nj = 0; nj < 4; nj++)
                    mma16(acc[mi][nj], af[mi], bf[nj >> 1][(nj & 1) * 2], bf[nj >> 1][(nj & 1) * 2 + 1]);
        }
        __syncthreads();
    }

#pragma unroll
    for (int mi = 0; mi < 4; mi++) {
        int m_lo = m0 + wm * 64 + mi * 16 + g;
        int m_hi = m_lo + 8;
#pragma unroll
        for (int nj = 0; nj < 4; nj++) {
            int n = n0 + wn * 32 + nj * 8 + 2 * cq;
            float b0 = bias[n] * bscale, b1 = bias[n + 1] * bscale;
            float v00 = acc[mi][nj][0] + b0, v01 = acc[mi][nj][1] + b1;
            float v10 = acc[mi][nj][2] + b0, v11 = acc[mi][nj][3] + b1;
            if (MODE == 0) {
                __half* out = (__half*)outp;
                int h = n >> 6, e = n & 63;
                int bb = m_lo >> 11, s = m_lo & 2047;
                *(half2*)(out + (((size_t)(bb * Hsz + h) * Ssz) + s) * HDsz + e) =
                    __floats2half2_rn(v00, v01);
                bb = m_hi >> 11; s = m_hi & 2047;
                *(half2*)(out + (((size_t)(bb * Hsz + h) * Ssz) + s) * HDsz + e) =
                    __floats2half2_rn(v10, v11);
            } else if (MODE == 1) {
                __half* out = (__half*)outp;
                int h = n >> 6, e = n & 63;
                int bb = m_lo >> 11, s = m_lo & 2047;
                size_t base = ((size_t)(bb * Hsz + h) * HDsz + e) * Ssz + s;
                out[base]       = __float2half_rn(v00);
                out[base + Ssz] = __float2half_rn(v01);
                bb = m_hi >> 11; s = m_hi & 2047;
                base = ((size_t)(bb * Hsz + h) * HDsz + e) * Ssz + s;
                out[base]       = __float2half_rn(v10);
                out[base + Ssz] = __float2half_rn(v11);
            } else {
                float* out = (float*)outp;
                *(float2*)(out + (size_t)m_lo * Dsz + n) = make_float2(v00, v01);
                *(float2*)(out + (size_t)m_hi * Dsz + n) = make_float2(v10, v11);
            }
        }
    }
}

__global__ __launch_bounds__(256) void proj_qk_kernel(
    const float* __restrict__ bq, const float* __restrict__ bk)
{
    const int which = blockIdx.z;
    const __half* W   = g_wh + (size_t)which * Dsz * Dsz;
    const float* bias = (which == 0) ? bq : bk;
    float bscale      = (which == 0) ? QSCALE : 1.0f;
    __half* out       = (which == 0) ? g_q : g_k;
    gemm_body<0>(g_xh, W, bias, bscale, out);
}

__global__ __launch_bounds__(256) void proj_v_kernel(const float* __restrict__ bv)
{
    gemm_body<1>(g_xh, g_wh + 2 * (size_t)Dsz * Dsz, bv, 1.0f, g_v);
}

__global__ __launch_bounds__(256) void outproj_kernel(
    const float* __restrict__ bo, float* __restrict__ out)
{
    gemm_body<2>(g_zh, g_wh + 3 * (size_t)Dsz * Dsz, bo, 1.0f, out);
}

// ================= fused causal flash attention (base-2 softmax) =================

#define AQT 128
#define QOFF 0
#define QWORDS (128 * SROW)
#define KOFF QWORDS
#define KBUF (64 * SROW)
#define VOFF (KOFF + 2 * KBUF)
#define ATT_SMEM_WORDS (QWORDS + 4 * KBUF)
#define ATT_SMEM_BYTES (ATT_SMEM_WORDS * 4)   // 55296

__global__ __launch_bounds__(256) void attn_kernel()
{
    extern __shared__ uint32_t smw[];
    const uint32_t sbase = (uint32_t)__cvta_generic_to_shared(smw);

    const int tid = threadIdx.x;
    const int w = tid >> 5, lane = tid & 31;
    const int g = lane >> 2, cq = lane & 3;
    const int qt = gridDim.x - 1 - blockIdx.x;   // heavy tiles first
    const int q0 = qt * AQT;
    const int h = blockIdx.y, b = blockIdx.z;

    const size_t bh = (size_t)(b * Hsz + h);
    const __half* Qp = g_q + (bh * Ssz + q0) * HDsz;
    const __half* Kp = g_k + bh * Ssz * HDsz;
    const __half* Vp = g_v + bh * HDsz * Ssz;

    const uint32_t offB = (uint32_t)(((lane & 7) + 8 * (lane >> 4)) * SROW * 4
                                     + ((lane >> 3) & 1) * 16);

    auto issueK = [&](int buf, int k0) {
#pragma unroll
        for (int p = 0; p < 2; p++) {
            int idx = tid + p * 256;
            int row = idx >> 3;
            int c   = idx & 7;
            uint32_t off = (uint32_t)((KOFF + buf * KBUF + row * SROW + c * 4) * 4);
            cp16(sbase + off, Kp + ((size_t)(k0 + row)) * HDsz + c * 8);
        }
    };
    auto issueV = [&](int buf, int k0) {
#pragma unroll
        for (int p = 0; p < 2; p++) {
            int idx = tid + p * 256;
            int row = idx >> 3;
            int c   = idx & 7;
            uint32_t off = (uint32_t)((VOFF + buf * KBUF + row * SROW + c * 4) * 4);
            cp16(sbase + off, Vp + (size_t)row * Ssz + k0 + c * 8);
        }
    };

    {
#pragma unroll
        for (int p = 0; p < 4; p++) {
            int idx = tid + p * 256;
            int row = idx >> 3;
            int c   = idx & 7;
            uint32_t off = (uint32_t)((QOFF + row * SROW + c * 4) * 4);
            cp16(sbase + off, Qp + (size_t)row * HDsz + c * 8);
        }
        issueK(0, 0);
        issueV(0, 0);
        asm volatile("cp.async.commit_group;");
    }

    float o[8][4];
#pragma unroll
    for (int nf = 0; nf < 8; nf++)
#pragma unroll
        for (int t = 0; t < 4; t++) o[nf][t] = 0.f;
    float m_lo = -1e30f, m_hi = -1e30f, l_lo = 0.f, l_hi = 0.f;

    uint32_t qa[4][4];
    const int nkt = (q0 + AQT) / 64;
    const int q_lo = q0 + w * 16 + g;
    const int q_hi = q_lo + 8;
    const int warp_min_row = q0 + w * 16;

    for (int jt = 0; jt < nkt; jt++) {
        const int k0 = jt * 64;
        const int buf = jt & 1;
        if (jt + 1 < nkt) {
            issueK(buf ^ 1, k0 + 64);
            issueV(buf ^ 1, k0 + 64);
            asm volatile("cp.async.commit_group;");
            asm volatile("cp.async.wait_group 1;");
        } else {
            asm volatile("cp.async.wait_group 0;");
        }
        __syncthreads();

        if (jt == 0) {
            const int r = w * 16 + g;
#pragma unroll
            for (int kk = 0; kk < 4; kk++) {
                const uint32_t* p0 = smw + QOFF + r * SROW + kk * 8 + cq;
                qa[kk][0] = p0[0];
                qa[kk][1] = p0[8 * SROW];
                qa[kk][2] = p0[4];
                qa[kk][3] = p0[8 * SROW + 4];
            }
        }

        // S = Q @ K^T (already in log2 domain; scale folded into Wq/bq)
        float s[8][4];
#pragma unroll
        for (int nf = 0; nf < 8; nf++)
#pragma unroll
            for (int t = 0; t < 4; t++) s[nf][t] = 0.f;

        const uint32_t kBuf = sbase + (uint32_t)((KOFF + buf * KBUF) * 4);
#pragma unroll
        for (int kk = 0; kk < 4; kk++) {
#pragma unroll
            for (int pf = 0; pf < 4; pf++) {
                uint32_t bf[4];
                ldsm4(bf, kBuf + (uint32_t)(pf * 16 * SROW * 4 + kk * 32) + offB);
                mma16(s[2 * pf],     qa[kk], bf[0], bf[1]);
                mma16(s[2 * pf + 1], qa[kk], bf[2], bf[3]);
            }
        }

        // causal mask
        const bool diag = (k0 + 63 > warp_min_row);
        if (diag) {
#pragma unroll
            for (int nf = 0; nf < 8; nf++) {
                int n0c = k0 + nf * 8 + 2 * cq;
                if (n0c     > q_lo) s[nf][0] = -1e30f;
                if (n0c + 1 > q_lo) s[nf][1] = -1e30f;
                if (n0c     > q_hi) s[nf][2] = -1e30f;
                if (n0c + 1 > q_hi) s[nf][3] = -1e30f;
            }
        }

        // row max (quad shuffles)
        float mx0 = -1e30f, mx1 = -1e30f;
#pragma unroll
        for (int nf = 0; nf < 8; nf++) {
            mx0 = fmaxf(mx0, fmaxf(s[nf][0], s[nf][1]));
            mx1 = fmaxf(mx1, fmaxf(s[nf][2], s[nf][3]));
        }
        mx0 = fmaxf(mx0, __shfl_xor_sync(0xffffffffu, mx0, 1));
        mx0 = fmaxf(mx0, __shfl_xor_sync(0xffffffffu, mx0, 2));
        mx1 = fmaxf(mx1, __shfl_xor_sync(0xffffffffu, mx1, 1));
        mx1 = fmaxf(mx1, __shfl_xor_sync(0xffffffffu, mx1, 2));

        float mn0 = fmaxf(m_lo, mx0), mn1 = fmaxf(m_hi, mx1);
        float corr0 = ex2f(m_lo - mn0), corr1 = ex2f(m_hi - mn1);
        m_lo = mn0; m_hi = mn1;

        // P = 2^(s - m), packed fp16x2 (these ARE the PV A-frag halves)
        uint32_t p0r[8], p1r[8];
#pragma unroll
        for (int nf = 0; nf < 8; nf++) {
            p0r[nf] = h2ex2(packh2(s[nf][0] - mn0, s[nf][1] - mn0));
            p1r[nf] = h2ex2(packh2(s[nf][2] - mn1, s[nf][3] - mn1));
        }

#pragma unroll
        for (int nf = 0; nf < 8; nf++) {
            o[nf][0] *= corr0; o[nf][1] *= corr0;
            o[nf][2] *= corr1; o[nf][3] *= corr1;
        }

        // O += P @ V ; row-sum l via ones-column MMA
        const uint32_t vBuf = sbase + (uint32_t)((VOFF + buf * KBUF) * 4);
        float lacc[4] = {0.f, 0.f, 0.f, 0.f};
#pragma unroll
        for (int kk = 0; kk < 4; kk++) {
            uint32_t pa[4] = { p0r[2 * kk], p1r[2 * kk], p0r[2 * kk + 1], p1r[2 * kk + 1] };
            mma16(lacc, pa, ONE2, ONE2);
#pragma unroll
            for (int pf = 0; pf < 4; pf++) {
                uint32_t bf[4];
                ldsm4(bf, vBuf + (uint32_t)(pf * 16 * SROW * 4 + kk * 32) + offB);
                mma16(o[2 * pf],     pa, bf[0], bf[1]);
                mma16(o[2 * pf + 1], pa, bf[2], bf[3]);
            }
        }
        l_lo = l_lo * corr0 + lacc[0];
        l_hi = l_hi * corr1 + lacc[2];

        __syncthreads();
    }

    const float inv0 = 1.f / l_lo, inv1 = 1.f / l_hi;
    __half* zlo = g_zh + ((size_t)b * Ssz + q_lo) * Dsz + h * HDsz;
    __half* zhi = g_zh + ((size_t)b * Ssz + q_hi) * Dsz + h * HDsz;
#pragma unroll
    for (int nf = 0; nf < 8; nf++) {
        int cc = nf * 8 + 2 * cq;
        *(half2*)(zlo + cc) = __floats2half2_rn(o[nf][0] * inv0, o[nf][1] * inv0);
        *(half2*)(zhi + cc) = __floats2half2_rn(o[nf][2] * inv1, o[nf][3] * inv1);
    }
}

// ================= launch =================

extern "C" void kernel_launch(void* const* d_in, const int* in_sizes, int n_in,
                              void* d_out, int out_size)
{
    (void)in_sizes; (void)n_in; (void)out_size;
    const float* X  = (const float*)d_in[0];
    const float* Wq = (const float*)d_in[1];
    const float* bq = (const float*)d_in[2];
    const float* Wk = (const float*)d_in[3];
    const float* bk = (const float*)d_in[4];
    const float* Wv = (const float*)d_in[5];
    const float* bv = (const float*)d_in[6];
    const float* Wo = (const float*)d_in[7];
    const float* bo = (const float*)d_in[8];
    float* out = (float*)d_out;

    cudaFuncSetAttribute(proj_qk_kernel,
                         cudaFuncAttributeMaxDynamicSharedMemorySize, GEMM_SMEM_BYTES);
    cudaFuncSetAttribute(proj_v_kernel,
                         cudaFuncAttributeMaxDynamicSharedMemorySize, GEMM_SMEM_BYTES);
    cudaFuncSetAttribute(outproj_kernel,
                         cudaFuncAttributeMaxDynamicSharedMemorySize, GEMM_SMEM_BYTES);
    cudaFuncSetAttribute(attn_kernel,
                         cudaFuncAttributeMaxDynamicSharedMemorySize, ATT_SMEM_BYTES);

    preround_kernel<<<dim3(1024, 1, 5), 256>>>(X, Wq, Wk, Wv, Wo);

    proj_qk_kernel<<<dim3(Dsz / 128, Msz / 128, 2), 256, GEMM_SMEM_BYTES>>>(bq, bk);
    proj_v_kernel<<<dim3(Dsz / 128, Msz / 128, 1), 256, GEMM_SMEM_BYTES>>>(bv);

    attn_kernel<<<dim3(Ssz / AQT, Hsz, Bsz), 256, ATT_SMEM_BYTES>>>();

    outproj_kernel<<<dim3(Dsz / 128, Msz / 128, 1), 256, GEMM_SMEM_BYTES>>>(bo, out);
}